// round 16
// baseline (speedup 1.0000x reference)
#include <cuda_runtime.h>
#include <cuda_bf16.h>

#define BATCH    16
#define TDIM     1024
#define DDIM     1024
#define RADIUS   15
#define NBLOCKS  2048
#define ROW_TOTAL (64 * BATCH * 5)
#define TAU0     2.2f

typedef unsigned long long ull;

__device__ int g_counts[BATCH * DDIM];
__device__ int g_done;

__device__ __forceinline__ unsigned sortable(float f) {
    unsigned u = __float_as_uint(f);
    return u ^ (((unsigned)((int)u >> 31)) | 0x80000000u);
}
__device__ __forceinline__ float unsortable(unsigned s) {
    unsigned u = (s & 0x80000000u) ? (s ^ 0x80000000u) : ~s;
    return __uint_as_float(u);
}
__device__ __forceinline__ float comp4(float4 v, int j) {
    return (j == 0) ? v.x : (j == 1) ? v.y : (j == 2) ? v.z : v.w;
}

// R11 measured-best selection body; memory path changed only:
//  - streaming loads via __ldcg (L2-direct, no L1 allocation/pollution)
//  - per-warp rotated chunk order (warpId&7) to decorrelate queue bursts
// One warp per row, 32 elems/lane, 8 LDG.128 (MLP=8), branchless elementwise
// mask, bit-driven extraction (cached reloads -> L1 after first touch), exact
// top-5 with lax.top_k tie-break. Certificate: >=5 lanes hold a candidate =>
// v5 >= TAU0 (cold exact knockout fallback otherwise). Fused conv epilogue +
// monotone poll-sum barrier (no gpu-scope fences: CCTL.IVALL flushes L1).
__global__ void __launch_bounds__(256, 6) fused_kernel(const float* __restrict__ in,
                                                       float* __restrict__ out) {
    const unsigned FULL = 0xFFFFFFFFu;
    int warp = (blockIdx.x * 256 + threadIdx.x) >> 5;   // row id [0, 16384)
    int lane = threadIdx.x & 31;
    int g = (warp & (TDIM - 1)) >> 6;
    int rot = warp & 7;                                  // per-warp chunk rotation

    const float* rowbase = in + (size_t)warp * DDIM;
    const float4* p = (const float4*)rowbase + lane;

    // ---- Pass 1: 8 independent LDG.128.CG (rotated order), branchless mask ----
    // chunk c covers element indices 128*c + 4*lane .. +3  (bit b = 4c+j)
    unsigned m = 0;
    {
        float4 q[8];
#pragma unroll
        for (int i = 0; i < 8; i++) {
            int c = (i + rot) & 7;
            q[i] = __ldcg(p + c * 32);                  // L2-direct, no L1 fill
        }
#pragma unroll
        for (int i = 0; i < 8; i++) {
            int c = (i + rot) & 7;
#pragma unroll
            for (int j = 0; j < 4; j++) {
                if (comp4(q[i], j) >= TAU0) m |= 1u << (c * 4 + j);
            }
        }
    }

    // ---- Certificate: >=5 lanes with candidates => v5 >= TAU0 ----
    unsigned hasc = __ballot_sync(FULL, m != 0);
    if (__builtin_expect(__popc(hasc) < 5, 0)) {
        // ---- Cold exact fallback: knockout tau (cached reloads), re-mask ----
        float4 q[8];
#pragma unroll
        for (int c = 0; c < 8; c++) q[c] = p[c * 32];
        float lmax = __int_as_float(0xFF800000);
#pragma unroll
        for (int c = 0; c < 8; c++)
            lmax = fmaxf(lmax, fmaxf(fmaxf(q[c].x, q[c].y), fmaxf(q[c].z, q[c].w)));
        unsigned s = sortable(lmax);
        unsigned tau_s = 0;
#pragma unroll
        for (int r = 0; r < 5; r++) {
            unsigned best = __reduce_max_sync(FULL, s);
            tau_s = best;
            if (s == best) s = 0;   // drop ties: tau only shrinks (still a valid bound)
        }
        float tauf = unsortable(tau_s);
        m = 0;
#pragma unroll
        for (int c = 0; c < 8; c++) {
#pragma unroll
            for (int j = 0; j < 4; j++) {
                if (comp4(q[c], j) >= tauf) m |= 1u << (c * 4 + j);
            }
        }
    }
    int cnt = __popc(m);   // this lane's candidate count

    // ---- Phase C: per-lane best key via bit walk (cached scalar reloads) ----
    // key = (sortable(value) << 10) | (1023 - idx): value-major, lowest-index-wins.
    ull ck = 0;
    {
        unsigned mm = m;
        while (mm) {
            int b = __ffs(mm) - 1;
            mm &= mm - 1;
            int idx = 4 * lane + ((b >> 2) << 7) + (b & 3);
            float f = rowbase[idx];                     // fills L1 on first touch
            ull key = ((ull)sortable(f) << 10) | (unsigned)(1023 - idx);
            if (key > ck) ck = key;
        }
    }

    // ---- Phase D: exact top-5 extraction (value, lowest-index tie-break) ----
    int myidx = 0;
#pragma unroll
    for (int r = 0; r < 5; r++) {
        unsigned hi = (unsigned)(ck >> 10);
        unsigned bestv = __reduce_max_sync(FULL, hi);
        unsigned myinv = (unsigned)(ck & 1023u);
        unsigned inv_c = (hi == bestv) ? myinv : 0u;
        unsigned besti = __reduce_max_sync(FULL, inv_c);
        if (lane == r) myidx = 1023 - (int)besti;
        if (hi == bestv && myinv == besti) {            // unique winner lane
            cnt--;
            ull ub = ck;
            ull nk = 0;
            if (cnt > 0) {                               // rescan own bits for next-best
                unsigned mm = m;
                while (mm) {
                    int b = __ffs(mm) - 1;
                    mm &= mm - 1;
                    int idx = 4 * lane + ((b >> 2) << 7) + (b & 3);
                    float f = rowbase[idx];             // L1-hot after Phase C
                    ull key = ((ull)sortable(f) << 10) | (unsigned)(1023 - idx);
                    if (key < ub && key > nk) nk = key;
                }
            }
            ck = nk;
        }
    }

    if (lane < 5) atomicAdd(&g_counts[g * DDIM + myidx], 1);

    // ================= epilogue: last 16 ticket-takers run the conv =================
    __shared__ int s_ticket;
    __syncthreads();
    if (threadIdx.x == 0) s_ticket = atomicAdd(&g_done, 1);
    __syncthreads();
    int ticket = s_ticket;
    if (ticket < NBLOCKS - BATCH) return;

    if (ticket == NBLOCKS - 1 && threadIdx.x == 0) g_done = 0;  // all increments applied
    int crow = ticket - (NBLOCKS - BATCH);
    int tid = threadIdx.x;

    __shared__ float srow[DDIM + 2 * RADIUS];
    __shared__ float w[2 * RADIUS + 1];
    __shared__ int wsum[8];
    __shared__ int s_sum;

    if (tid < 2 * RADIUS + 1) {
        int k = tid - RADIUS;
        w[tid] = 0.19947114020071635f * expf(-0.125f * (float)(k * k));
    }
    if (tid < RADIUS) { srow[tid] = 0.0f; srow[DDIM + RADIUS + tid] = 0.0f; }

    // Poll-sum barrier: monotone counts + total match == consistent final snapshot.
    const int4* rowp = (const int4*)(g_counts + crow * DDIM);
    while (true) {
        int4 c4 = __ldcg(rowp + tid);                   // L2-coherent, bypass L1
        srow[RADIUS + tid * 4 + 0] = (float)c4.x;
        srow[RADIUS + tid * 4 + 1] = (float)c4.y;
        srow[RADIUS + tid * 4 + 2] = (float)c4.z;
        srow[RADIUS + tid * 4 + 3] = (float)c4.w;
        int part = c4.x + c4.y + c4.z + c4.w;
#pragma unroll
        for (int off = 16; off; off >>= 1) part += __shfl_xor_sync(FULL, part, off);
        if ((tid & 31) == 0) wsum[tid >> 5] = part;
        __syncthreads();
        if (tid == 0) {
            int t = 0;
#pragma unroll
            for (int i = 0; i < 8; i++) t += wsum[i];
            s_sum = t;
        }
        __syncthreads();
        if (s_sum == ROW_TOTAL) break;
        __nanosleep(100);
    }

    ((int4*)(g_counts + crow * DDIM))[tid] = make_int4(0, 0, 0, 0);

    float4 acc;
#pragma unroll
    for (int i = 0; i < 4; i++) {
        int d = tid * 4 + i;
        float a = 0.0f;
#pragma unroll
        for (int k = 0; k < 2 * RADIUS + 1; k++) a += srow[d + k] * w[k];
        ((float*)&acc)[i] = a;
    }
    ((float4*)(out + crow * DDIM))[tid] = acc;
}

extern "C" void kernel_launch(void* const* d_in, const int* in_sizes, int n_in,
                              void* d_out, int out_size) {
    const float* in = (const float*)d_in[0];
    float* out = (float*)d_out;
    fused_kernel<<<NBLOCKS, 256>>>(in, out);
}

// round 17
// speedup vs baseline: 1.0766x; 1.0766x over previous
#include <cuda_runtime.h>
#include <cuda_bf16.h>

#define BATCH    16
#define TDIM     1024
#define DDIM     1024
#define RADIUS   15
#define NBLOCKS  2048
#define EPI_BLKS 64                      // 4 conv blocks per g-row
#define ROW_TOTAL (64 * BATCH * 5)
#define TAU0     2.2f

typedef unsigned long long ull;

__device__ int g_counts[BATCH * DDIM];
__device__ int g_done;                   // completion ticket counter
__device__ int g_rowdone[BATCH];         // per-row sibling completion counters

__device__ __forceinline__ unsigned sortable(float f) {
    unsigned u = __float_as_uint(f);
    return u ^ (((unsigned)((int)u >> 31)) | 0x80000000u);
}
__device__ __forceinline__ float unsortable(unsigned s) {
    unsigned u = (s & 0x80000000u) ? (s ^ 0x80000000u) : ~s;
    return __uint_as_float(u);
}
__device__ __forceinline__ float comp4(float4 v, int j) {
    return (j == 0) ? v.x : (j == 1) ? v.y : (j == 2) ? v.z : v.w;
}

// R11 measured-best main phase, verbatim: one warp per row, 32 elems/lane,
// 8 LDG.128 kept live (MLP=8), branchless elementwise candidate mask,
// bit-driven extraction with L1-hot scalar reloads, exact top-5 with
// lax.top_k (value, lowest-index) tie-break. Certificate: >=5 lanes hold a
// candidate => >=5 elements >= TAU0 => v5 >= TAU0 => candidates contain the
// exact top-5; cold exact knockout fallback otherwise.
// Epilogue: last 64 ticket-takers run the conv, 4 blocks per row, each
// polling the monotone row total (==ROW_TOTAL <=> consistent final snapshot),
// computing a quarter of the outputs; the 4th finisher zeroes the row.
// No gpu-scope fences anywhere (CCTL.IVALL flushes L1 chip-wide on sm_103a).
__global__ void __launch_bounds__(256, 6) fused_kernel(const float* __restrict__ in,
                                                       float* __restrict__ out) {
    const unsigned FULL = 0xFFFFFFFFu;
    int warp = (blockIdx.x * 256 + threadIdx.x) >> 5;   // row id [0, 16384)
    int lane = threadIdx.x & 31;
    int g = (warp & (TDIM - 1)) >> 6;

    const float* rowbase = in + (size_t)warp * DDIM;
    const float4* p = (const float4*)rowbase + lane;

    // ---- Pass 1: 8 independent LDG.128, branchless candidate mask ----
    // element index for bit b (=4c+j): 4*lane + 128*(b>>2) + (b&3)
    unsigned m = 0;
    {
        float4 q[8];
#pragma unroll
        for (int c = 0; c < 8; c++) q[c] = p[c * 32];
#pragma unroll
        for (int c = 0; c < 8; c++) {
#pragma unroll
            for (int j = 0; j < 4; j++) {
                if (comp4(q[c], j) >= TAU0) m |= 1u << (c * 4 + j);
            }
        }
    }

    // ---- Certificate: >=5 lanes with candidates => v5 >= TAU0 ----
    unsigned hasc = __ballot_sync(FULL, m != 0);
    if (__builtin_expect(__popc(hasc) < 5, 0)) {
        // ---- Cold exact fallback: knockout tau from L1 reloads, re-mask ----
        float4 q[8];
#pragma unroll
        for (int c = 0; c < 8; c++) q[c] = p[c * 32];
        float lmax = __int_as_float(0xFF800000);
#pragma unroll
        for (int c = 0; c < 8; c++)
            lmax = fmaxf(lmax, fmaxf(fmaxf(q[c].x, q[c].y), fmaxf(q[c].z, q[c].w)));
        unsigned s = sortable(lmax);
        unsigned tau_s = 0;
#pragma unroll
        for (int r = 0; r < 5; r++) {
            unsigned best = __reduce_max_sync(FULL, s);
            tau_s = best;
            if (s == best) s = 0;   // drop ties: tau only shrinks (still a valid bound)
        }
        float tauf = unsortable(tau_s);
        m = 0;
#pragma unroll
        for (int c = 0; c < 8; c++) {
#pragma unroll
            for (int j = 0; j < 4; j++) {
                if (comp4(q[c], j) >= tauf) m |= 1u << (c * 4 + j);
            }
        }
    }
    int cnt = __popc(m);   // this lane's candidate count

    // ---- Phase C: per-lane best key via bit walk (E[bits] = 0.44/lane) ----
    // key = (sortable(value) << 10) | (1023 - idx): value-major, lowest-index-wins.
    ull ck = 0;
    {
        unsigned mm = m;
        while (mm) {
            int b = __ffs(mm) - 1;
            mm &= mm - 1;
            int idx = 4 * lane + ((b >> 2) << 7) + (b & 3);
            float f = rowbase[idx];                     // L1-hot scalar reload
            ull key = ((ull)sortable(f) << 10) | (unsigned)(1023 - idx);
            if (key > ck) ck = key;
        }
    }

    // ---- Phase D: exact top-5 extraction (value, lowest-index tie-break) ----
    int myidx = 0;
#pragma unroll
    for (int r = 0; r < 5; r++) {
        unsigned hi = (unsigned)(ck >> 10);
        unsigned bestv = __reduce_max_sync(FULL, hi);
        unsigned myinv = (unsigned)(ck & 1023u);
        unsigned inv_c = (hi == bestv) ? myinv : 0u;
        unsigned besti = __reduce_max_sync(FULL, inv_c);
        if (lane == r) myidx = 1023 - (int)besti;
        if (hi == bestv && myinv == besti) {            // unique winner lane
            cnt--;
            ull ub = ck;
            ull nk = 0;
            if (cnt > 0) {                               // rescan own bits for next-best
                unsigned mm = m;
                while (mm) {
                    int b = __ffs(mm) - 1;
                    mm &= mm - 1;
                    int idx = 4 * lane + ((b >> 2) << 7) + (b & 3);
                    float f = rowbase[idx];
                    ull key = ((ull)sortable(f) << 10) | (unsigned)(1023 - idx);
                    if (key < ub && key > nk) nk = key;
                }
            }
            ck = nk;
        }
    }

    if (lane < 5) atomicAdd(&g_counts[g * DDIM + myidx], 1);

    // ============ epilogue: last 64 ticket-takers, 4 conv blocks per row ============
    __shared__ int s_ticket;
    __syncthreads();
    if (threadIdx.x == 0) s_ticket = atomicAdd(&g_done, 1);
    __syncthreads();
    int ticket = s_ticket;
    if (ticket < NBLOCKS - EPI_BLKS) return;

    if (ticket == NBLOCKS - 1 && threadIdx.x == 0) g_done = 0;  // all increments applied
    int eslot = ticket - (NBLOCKS - EPI_BLKS);
    int crow = eslot >> 2;            // g-row [0,16)
    int quarter = eslot & 3;          // output quarter [0,4)
    int tid = threadIdx.x;

    __shared__ float srow[DDIM + 2 * RADIUS];
    __shared__ float w[2 * RADIUS + 1];
    __shared__ int wsum[8];
    __shared__ int s_sum;

    if (tid < 2 * RADIUS + 1) {
        int k = tid - RADIUS;
        w[tid] = 0.19947114020071635f * expf(-0.125f * (float)(k * k));
    }
    if (tid < RADIUS) { srow[tid] = 0.0f; srow[DDIM + RADIUS + tid] = 0.0f; }

    // Poll-sum barrier: monotone counts + total match == consistent final snapshot.
    // Full row staged (conv quarters need cross-boundary halos anyway).
    const int4* rowp = (const int4*)(g_counts + crow * DDIM);
    while (true) {
        int4 c4 = __ldcg(rowp + tid);                   // L2-coherent, bypass L1
        srow[RADIUS + tid * 4 + 0] = (float)c4.x;
        srow[RADIUS + tid * 4 + 1] = (float)c4.y;
        srow[RADIUS + tid * 4 + 2] = (float)c4.z;
        srow[RADIUS + tid * 4 + 3] = (float)c4.w;
        int part = c4.x + c4.y + c4.z + c4.w;
#pragma unroll
        for (int off = 16; off; off >>= 1) part += __shfl_xor_sync(FULL, part, off);
        if ((tid & 31) == 0) wsum[tid >> 5] = part;
        __syncthreads();
        if (tid == 0) {
            int t = 0;
#pragma unroll
            for (int i = 0; i < 8; i++) t += wsum[i];
            s_sum = t;
        }
        __syncthreads();
        if (s_sum == ROW_TOTAL) break;
        __nanosleep(100);
    }

    // conv: this block computes outputs [quarter*256, quarter*256+256).
    {
        int d = quarter * 256 + tid;
        float a = 0.0f;
#pragma unroll
        for (int k = 0; k < 2 * RADIUS + 1; k++) a += srow[d + k] * w[k];
        out[crow * DDIM + d] = a;
    }

    // Sibling completion: 4th finisher zeroes the row + resets the counter.
    // (Zeroing only after ALL siblings have passed their poll — no poll deadlock.)
    __syncthreads();
    if (tid == 0) {
        int done = atomicAdd(&g_rowdone[crow], 1);
        s_sum = done;
    }
    __syncthreads();
    if (s_sum == 3) {                 // last sibling for this row
        ((int4*)(g_counts + crow * DDIM))[tid] = make_int4(0, 0, 0, 0);
        if (tid == 0) g_rowdone[crow] = 0;
    }
}

extern "C" void kernel_launch(void* const* d_in, const int* in_sizes, int n_in,
                              void* d_out, int out_size) {
    const float* in = (const float*)d_in[0];
    float* out = (float*)d_out;
    fused_kernel<<<NBLOCKS, 256>>>(in, out);
}